// round 8
// baseline (speedup 1.0000x reference)
#include <cuda_runtime.h>

#define NN 50000
#define EE 600000
#define CC 128
#define CE 8
#define NUM_CELLS 854
#define NEG_SLOPE 0.2f
#define LN_EPS 1e-5f

struct Vec8 { const float* p[8]; };

// ------- scratch: __device__ symbols, referenced ONLY inside device code -----
__device__ __align__(16) float g_h[NN * CC];      // h (layer) / x2 (in-place)
__device__ __align__(16) float g_cellW[NUM_CELLS * CC];
__device__ float g_as[NN];
__device__ float g_ad[NN];
__device__ float g_denom[NN];
__device__ int   g_mode_ei;     // 0=int32 1=int64 2=float32
__device__ int   g_mode_cid;
__device__ int g_r_as1, g_r_ad1, g_r_as2, g_r_ad2;
__device__ int g_r_b1, g_r_lng, g_r_lnb, g_r_b2;

// ---------------- index dtype detection --------------------------------------
__global__ void detect_kernel(const void* buf, int n, int maxval, int which) {
    __shared__ int ok64, ok32, okf;
    if (threadIdx.x == 0) { ok64 = 1; ok32 = 1; okf = 1; }
    __syncthreads();
    const long long* p64 = (const long long*)buf;
    const int* p32 = (const int*)buf;
    const float* pf = (const float*)buf;
    int half = n / 2;
    int stride = half / 1024; if (stride < 1) stride = 1;
    int b64 = 1, b32 = 1, bf = 1;
    for (int i = threadIdx.x; i < 1024; i += blockDim.x) {
        int idx = i * stride; if (idx >= half) idx = half - 1;
        long long v64 = p64[idx];
        int v32 = p32[idx];
        float vf = pf[idx];
        b64 &= (v64 >= 0 && v64 < maxval);
        b32 &= (v32 >= 0 && v32 < maxval);
        bf  &= (isfinite(vf) && vf >= 0.f && vf < (float)maxval &&
                vf == rintf(vf));
    }
    if (!b64) atomicAnd(&ok64, 0);
    if (!b32) atomicAnd(&ok32, 0);
    if (!bf)  atomicAnd(&okf, 0);
    __syncthreads();
    if (threadIdx.x == 0) {
        int m = ok64 ? 1 : (ok32 ? 0 : (okf ? 2 : 0));
        if (which == 0) g_mode_ei = m; else g_mode_cid = m;
    }
}

__device__ __forceinline__ int ld_idx(const void* p, int i, int mode) {
    if (mode == 1) return (int)((const long long*)p)[i];
    if (mode == 2) return (int)((const float*)p)[i];
    return ((const int*)p)[i];
}

__device__ __forceinline__ int clampi(int v, int hi) {
    v = (v < 0) ? 0 : v;
    return (v >= hi) ? hi - 1 : v;
}

// ---------------- classify the eight CC-length vectors -----------------------
__global__ void classify_kernel(Vec8 v) {
    __shared__ int isZ[8], isO[8];
    int t = threadIdx.x;
    int vec = t >> 5, lane = t & 31;
    if (vec < 8) {
        const float* pv = v.p[vec];
        int z = 1, o = 1;
        for (int i = lane; i < CC; i += 32) {
            float x = pv[i];
            z &= (x == 0.0f);
            o &= (x == 1.0f);
        }
#pragma unroll
        for (int off = 16; off; off >>= 1) {
            z &= __shfl_xor_sync(0xffffffffu, z, off);
            o &= __shfl_xor_sync(0xffffffffu, o, off);
        }
        if (lane == 0) { isZ[vec] = z; isO[vec] = o; }
    }
    __syncthreads();
    if (t == 0) {
        int zm = 0, om = 0;
        for (int i = 0; i < 8; i++) { zm |= isZ[i] << i; om |= isO[i] << i; }
        int as1 = 0, ad1 = 1, b1 = 2, lng = 3, lnb = 4, as2 = 5, ad2 = 6, b2 = 7;
        if (zm == 0x70 && om == 0x80) {          // alphabetical
            ad1 = 0; ad2 = 1; as1 = 2; as2 = 3; b1 = 4; b2 = 5; lnb = 6; lng = 7;
        } else if (zm == 0x29 && om == 0x10) {   // reversed dict
            b2 = 0; ad2 = 1; as2 = 2; lnb = 3; lng = 4; b1 = 5; ad1 = 6; as1 = 7;
        } else if (zm == 0x0E && om == 0x01) {   // reversed alphabetical
            lng = 0; lnb = 1; b2 = 2; b1 = 3; as2 = 4; as1 = 5; ad2 = 6; ad1 = 7;
        }
        g_r_as1 = as1; g_r_ad1 = ad1; g_r_as2 = as2; g_r_ad2 = ad2;
        g_r_b1 = b1; g_r_lng = lng; g_r_lnb = lnb; g_r_b2 = b2;
    }
}

// ---------------- cell embedding folded into W1 ------------------------------
__global__ void cellw_kernel(const float* __restrict__ cell_emb,
                             const float* __restrict__ W1) {
    int cell = blockIdx.x;
    int c = threadIdx.x;
    float acc = 0.f;
#pragma unroll
    for (int j = 0; j < CE; j++)
        acc += cell_emb[cell * CE + j] * W1[(CC + j) * CC + c];
    g_cellW[cell * CC + c] = acc;
}

// ---------------- SGEMM: g_h = X @ W (+cellW); X = Xext or g_h (in place) ----
// 1024 threads = 8 rows x 128 cols. Rows staged to smem before any write, so
// X == g_h in-place is safe. W loads coalesced; W is L2/L1 resident.
__global__ void __launch_bounds__(1024) gemm_kernel(
        const float* Xext, const float* __restrict__ W,
        const void* __restrict__ cids, int addCell) {
    __shared__ float sX[8][CC];
    int rloc = threadIdx.x >> 7;
    int c = threadIdx.x & 127;
    int row = blockIdx.x * 8 + rloc;

    const float* X = Xext ? Xext : g_h;   // g_h resolved in DEVICE code
    sX[rloc][c] = X[row * CC + c];
    __syncthreads();

    float acc = 0.f;
#pragma unroll 8
    for (int k = 0; k < CC; k++)
        acc += sX[rloc][k] * W[k * CC + c];

    if (addCell) {
        int cid = clampi(ld_idx(cids, row, g_mode_cid), NUM_CELLS);
        acc += g_cellW[cid * CC + c];
    }
    g_h[row * CC + c] = acc;
}

// ---------------- node init: alpha dots, self-loop seed into outbuf ----------
__global__ void nodeinit_kernel(Vec8 v, int layer, float* outbuf) {
    int gid = (blockIdx.x * blockDim.x + threadIdx.x) >> 5;
    int lane = threadIdx.x & 31;
    if (gid >= NN) return;

    const float* a_src = v.p[(layer == 1) ? g_r_as1 : g_r_as2];
    const float* a_dst = v.p[(layer == 1) ? g_r_ad1 : g_r_ad2];

    const float4* H4 = (const float4*)g_h;
    float4 hv = H4[gid * 32 + lane];
    float s0 = a_src[lane * 4 + 0], s1 = a_src[lane * 4 + 1];
    float s2 = a_src[lane * 4 + 2], s3 = a_src[lane * 4 + 3];
    float d0 = a_dst[lane * 4 + 0], d1 = a_dst[lane * 4 + 1];
    float d2 = a_dst[lane * 4 + 2], d3 = a_dst[lane * 4 + 3];

    float ps = hv.x * s0 + hv.y * s1 + hv.z * s2 + hv.w * s3;
    float pd = hv.x * d0 + hv.y * d1 + hv.z * d2 + hv.w * d3;
#pragma unroll
    for (int off = 16; off; off >>= 1) {
        ps += __shfl_xor_sync(0xffffffffu, ps, off);
        pd += __shfl_xor_sync(0xffffffffu, pd, off);
    }
    float e = ps + pd;
    e = (e > 0.f) ? e : NEG_SLOPE * e;
    float w = expf(e);
    if (lane == 0) {
        g_as[gid] = ps;
        g_ad[gid] = pd;
        g_denom[gid] = w;
    }
    float* op = outbuf + gid * CC + lane * 4;
    op[0] = hv.x * w;
    op[1] = hv.y * w;
    op[2] = hv.z * w;
    op[3] = hv.w * w;
}

// ---------------- edge pass: scatter exp(e)*h[src] into outbuf[dst] ----------
__global__ void edge_kernel(const void* __restrict__ ei, float* outbuf) {
    int gid = (blockIdx.x * blockDim.x + threadIdx.x) >> 5;
    int lane = threadIdx.x & 31;
    if (gid >= EE) return;

    int mode = g_mode_ei;
    int src = clampi(ld_idx(ei, gid, mode), NN);
    int dst = clampi(ld_idx(ei, EE + gid, mode), NN);

    float e = g_as[src] + g_ad[dst];
    e = (e > 0.f) ? e : NEG_SLOPE * e;
    float ex = expf(e);
    if (lane == 0) atomicAdd(&g_denom[dst], ex);

    const float4* H4 = (const float4*)g_h;
    float4 hv = H4[src * 32 + lane];
    float* op = outbuf + dst * CC + lane * 4;
    // vectorized no-return reduction: 1 op instead of 4 (sm_90+)
    asm volatile("red.global.add.v4.f32 [%0], {%1, %2, %3, %4};"
                 :: "l"(op), "f"(hv.x * ex), "f"(hv.y * ex),
                    "f"(hv.z * ex), "f"(hv.w * ex)
                 : "memory");
}

// ---------------- layer-1 epilogue: divide, bias, LN, ELU -> g_h -------------
__global__ void final1_kernel(const float* outbuf, Vec8 v) {
    int gid = (blockIdx.x * blockDim.x + threadIdx.x) >> 5;
    int lane = threadIdx.x & 31;
    if (gid >= NN) return;

    const float* b1   = v.p[g_r_b1];
    const float* ln_g = v.p[g_r_lng];
    const float* ln_b = v.p[g_r_lnb];

    float inv = 1.f / g_denom[gid];
    const float* ip = outbuf + gid * CC + lane * 4;
    float o0 = ip[0] * inv + b1[lane * 4 + 0];
    float o1 = ip[1] * inv + b1[lane * 4 + 1];
    float o2 = ip[2] * inv + b1[lane * 4 + 2];
    float o3 = ip[3] * inv + b1[lane * 4 + 3];

    float s = o0 + o1 + o2 + o3;
    float sq = o0 * o0 + o1 * o1 + o2 * o2 + o3 * o3;
#pragma unroll
    for (int off = 16; off; off >>= 1) {
        s  += __shfl_xor_sync(0xffffffffu, s, off);
        sq += __shfl_xor_sync(0xffffffffu, sq, off);
    }
    float mu = s * (1.f / CC);
    float var = sq * (1.f / CC) - mu * mu;
    float rstd = rsqrtf(var + LN_EPS);

    float y0 = (o0 - mu) * rstd * ln_g[lane * 4 + 0] + ln_b[lane * 4 + 0];
    float y1 = (o1 - mu) * rstd * ln_g[lane * 4 + 1] + ln_b[lane * 4 + 1];
    float y2 = (o2 - mu) * rstd * ln_g[lane * 4 + 2] + ln_b[lane * 4 + 2];
    float y3 = (o3 - mu) * rstd * ln_g[lane * 4 + 3] + ln_b[lane * 4 + 3];
    y0 = (y0 > 0.f) ? y0 : expm1f(y0);
    y1 = (y1 > 0.f) ? y1 : expm1f(y1);
    y2 = (y2 > 0.f) ? y2 : expm1f(y2);
    y3 = (y3 > 0.f) ? y3 : expm1f(y3);

    float4* X4 = (float4*)g_h;
    X4[gid * 32 + lane] = make_float4(y0, y1, y2, y3);
}

// ---------------- layer-2 epilogue: in-place divide + bias on outbuf ---------
__global__ void final2_kernel(float* outbuf, Vec8 v) {
    int gid = (blockIdx.x * blockDim.x + threadIdx.x) >> 5;
    int lane = threadIdx.x & 31;
    if (gid >= NN) return;

    const float* b2 = v.p[g_r_b2];
    float inv = 1.f / g_denom[gid];
    float* p = outbuf + gid * CC + lane * 4;
    p[0] = p[0] * inv + b2[lane * 4 + 0];
    p[1] = p[1] * inv + b2[lane * 4 + 1];
    p[2] = p[2] * inv + b2[lane * 4 + 2];
    p[3] = p[3] * inv + b2[lane * 4 + 3];
}

// -----------------------------------------------------------------------------
extern "C" void kernel_launch(void* const* d_in, const int* in_sizes, int n_in,
                              void* d_out, int out_size) {
    // --- input remap by element count (verified: element counts, dict order) -
    int ix = 0, icid = 1, iei = 2, icemb = 3, iW1 = 4, iW2 = 10;
    int vecidx[8];
    int nvec = 0;
    {
        int fx = -1, fcid = -1, fei = -1, fcemb = -1, fW1 = -1, fW2 = -1;
        for (int i = 0; i < n_in; i++) {
            long long s = in_sizes[i];
            if (s == NN * CC) fx = (fx < 0) ? i : fx;
            else if (s == NN || s == 2 * NN) fcid = (fcid < 0) ? i : fcid;
            else if (s == 2LL * EE || s == 4LL * EE) fei = (fei < 0) ? i : fei;
            else if (s == NUM_CELLS * CE) fcemb = (fcemb < 0) ? i : fcemb;
            else if (s == (CC + CE) * CC) fW1 = (fW1 < 0) ? i : fW1;
            else if (s == CC * CC) fW2 = (fW2 < 0) ? i : fW2;
            else if (s == CC && nvec < 8) vecidx[nvec++] = i;
        }
        if (fx >= 0 && fcid >= 0 && fei >= 0 && fcemb >= 0 && fW1 >= 0 &&
            fW2 >= 0 && nvec == 8) {
            ix = fx; icid = fcid; iei = fei; icemb = fcemb; iW1 = fW1; iW2 = fW2;
        } else {
            ix = 0; icid = 1; iei = 2; icemb = 3; iW1 = 4; iW2 = 10;
            vecidx[0] = 5; vecidx[1] = 6; vecidx[2] = 7; vecidx[3] = 8;
            vecidx[4] = 9; vecidx[5] = 11; vecidx[6] = 12; vecidx[7] = 13;
        }
    }

    const float* x_base  = (const float*)d_in[ix];
    const void*  cids    = d_in[icid];
    const void*  ei      = d_in[iei];
    const float* cellemb = (const float*)d_in[icemb];
    const float* W1      = (const float*)d_in[iW1];
    const float* W2      = (const float*)d_in[iW2];
    Vec8 v;
    for (int j = 0; j < 8; j++) v.p[j] = (const float*)d_in[vecidx[j]];
    float* out = (float*)d_out;

    int gemm_blocks = NN / 8;
    int node_blocks = (NN * 32 + 255) / 256;
    int edge_blocks = (EE * 32 + 255) / 256;

    detect_kernel<<<1, 256>>>(ei, 2 * EE, NN, 0);
    detect_kernel<<<1, 256>>>(cids, NN, NUM_CELLS, 1);
    classify_kernel<<<1, 256>>>(v);
    cellw_kernel<<<NUM_CELLS, CC>>>(cellemb, W1);

    // ---- layer 1 (aggregate directly into d_out) ----
    gemm_kernel<<<gemm_blocks, 1024>>>(x_base, W1, cids, 1);
    nodeinit_kernel<<<node_blocks, 256>>>(v, 1, out);
    edge_kernel<<<edge_blocks, 256>>>(ei, out);
    final1_kernel<<<node_blocks, 256>>>(out, v);          // writes x2 -> g_h

    // ---- layer 2 (gemm in-place on g_h; aggregate into d_out) ----
    gemm_kernel<<<gemm_blocks, 1024>>>(nullptr, W2, cids, 0);
    nodeinit_kernel<<<node_blocks, 256>>>(v, 2, out);
    edge_kernel<<<edge_blocks, 256>>>(ei, out);
    final2_kernel<<<node_blocks, 256>>>(out, v);
}

// round 9
// speedup vs baseline: 1.2095x; 1.2095x over previous
#include <cuda_runtime.h>

#define NN 50000
#define EE 600000
#define CC 128
#define CE 8
#define NUM_CELLS 854
#define NEG_SLOPE 0.2f
#define LN_EPS 1e-5f
#define NCH 196            // ceil(NN/256)
#define FULL 0xffffffffu

struct Vec8 { const float* p[8]; };

// ------- scratch: __device__ symbols, referenced ONLY inside device code -----
__device__ __align__(16) float g_h[NN * CC];
__device__ __align__(16) float g_cellW[NUM_CELLS * CC];
__device__ float g_as[NN];
__device__ float g_ad[NN];
__device__ int g_rowptr[NN + 1];
__device__ int g_rowcnt[NN];
__device__ int g_fill[NN];
__device__ int g_bsum[NCH];
__device__ int g_esrc[EE];
__device__ int g_mode_ei;      // 0=int32 1=int64 2=float32
__device__ int g_mode_cid;
__device__ int g_r_as1, g_r_ad1, g_r_as2, g_r_ad2;
__device__ int g_r_b1, g_r_lng, g_r_lnb, g_r_b2;

// ---------------- index dtype detection --------------------------------------
__global__ void detect_kernel(const void* buf, int n, int maxval, int which) {
    __shared__ int ok64, ok32, okf;
    if (threadIdx.x == 0) { ok64 = 1; ok32 = 1; okf = 1; }
    __syncthreads();
    const long long* p64 = (const long long*)buf;
    const int* p32 = (const int*)buf;
    const float* pf = (const float*)buf;
    int half = n / 2;
    int stride = half / 1024; if (stride < 1) stride = 1;
    int b64 = 1, b32 = 1, bf = 1;
    for (int i = threadIdx.x; i < 1024; i += blockDim.x) {
        int idx = i * stride; if (idx >= half) idx = half - 1;
        long long v64 = p64[idx];
        int v32 = p32[idx];
        float vf = pf[idx];
        b64 &= (v64 >= 0 && v64 < maxval);
        b32 &= (v32 >= 0 && v32 < maxval);
        bf  &= (isfinite(vf) && vf >= 0.f && vf < (float)maxval &&
                vf == rintf(vf));
    }
    if (!b64) atomicAnd(&ok64, 0);
    if (!b32) atomicAnd(&ok32, 0);
    if (!bf)  atomicAnd(&okf, 0);
    __syncthreads();
    if (threadIdx.x == 0) {
        int m = ok64 ? 1 : (ok32 ? 0 : (okf ? 2 : 0));
        if (which == 0) g_mode_ei = m; else g_mode_cid = m;
    }
}

__device__ __forceinline__ int ld_idx(const void* p, int i, int mode) {
    if (mode == 1) return (int)((const long long*)p)[i];
    if (mode == 2) return (int)((const float*)p)[i];
    return ((const int*)p)[i];
}

__device__ __forceinline__ int clampi(int v, int hi) {
    v = (v < 0) ? 0 : v;
    return (v >= hi) ? hi - 1 : v;
}

// ---------------- classify the eight CC-length vectors -----------------------
__global__ void classify_kernel(Vec8 v) {
    __shared__ int isZ[8], isO[8];
    int t = threadIdx.x;
    int vec = t >> 5, lane = t & 31;
    if (vec < 8) {
        const float* pv = v.p[vec];
        int z = 1, o = 1;
        for (int i = lane; i < CC; i += 32) {
            float x = pv[i];
            z &= (x == 0.0f);
            o &= (x == 1.0f);
        }
#pragma unroll
        for (int off = 16; off; off >>= 1) {
            z &= __shfl_xor_sync(FULL, z, off);
            o &= __shfl_xor_sync(FULL, o, off);
        }
        if (lane == 0) { isZ[vec] = z; isO[vec] = o; }
    }
    __syncthreads();
    if (t == 0) {
        int zm = 0, om = 0;
        for (int i = 0; i < 8; i++) { zm |= isZ[i] << i; om |= isO[i] << i; }
        int as1 = 0, ad1 = 1, b1 = 2, lng = 3, lnb = 4, as2 = 5, ad2 = 6, b2 = 7;
        if (zm == 0x70 && om == 0x80) {          // alphabetical
            ad1 = 0; ad2 = 1; as1 = 2; as2 = 3; b1 = 4; b2 = 5; lnb = 6; lng = 7;
        } else if (zm == 0x29 && om == 0x10) {   // reversed dict
            b2 = 0; ad2 = 1; as2 = 2; lnb = 3; lng = 4; b1 = 5; ad1 = 6; as1 = 7;
        } else if (zm == 0x0E && om == 0x01) {   // reversed alphabetical
            lng = 0; lnb = 1; b2 = 2; b1 = 3; as2 = 4; as1 = 5; ad2 = 6; ad1 = 7;
        }
        g_r_as1 = as1; g_r_ad1 = ad1; g_r_as2 = as2; g_r_ad2 = ad2;
        g_r_b1 = b1; g_r_lng = lng; g_r_lnb = lnb; g_r_b2 = b2;
    }
}

// ---------------- cell embedding folded into W1 ------------------------------
__global__ void cellw_kernel(const float* __restrict__ cell_emb,
                             const float* __restrict__ W1) {
    int cell = blockIdx.x;
    int c = threadIdx.x;
    float acc = 0.f;
#pragma unroll
    for (int j = 0; j < CE; j++)
        acc += cell_emb[cell * CE + j] * W1[(CC + j) * CC + c];
    g_cellW[cell * CC + c] = acc;
}

// ---------------- CSR build --------------------------------------------------
__global__ void csr_zero_kernel() {
    int i = blockIdx.x * blockDim.x + threadIdx.x;
    if (i < NN) { g_rowcnt[i] = 0; g_fill[i] = 0; }
}

__global__ void csr_hist_kernel(const void* __restrict__ ei) {
    int e = blockIdx.x * blockDim.x + threadIdx.x;
    if (e >= EE) return;
    int dst = clampi(ld_idx(ei, EE + e, g_mode_ei), NN);
    atomicAdd(&g_rowcnt[dst], 1);
}

__global__ void csr_scan1_kernel() {
    __shared__ int sm[256];
    int i = blockIdx.x * 256 + threadIdx.x;
    sm[threadIdx.x] = (i < NN) ? g_rowcnt[i] : 0;
    __syncthreads();
    for (int s = 128; s; s >>= 1) {
        if (threadIdx.x < s) sm[threadIdx.x] += sm[threadIdx.x + s];
        __syncthreads();
    }
    if (threadIdx.x == 0) g_bsum[blockIdx.x] = sm[0];
}

__global__ void csr_scan2_kernel() {
    if (threadIdx.x == 0) {
        int run = 0;
        for (int b = 0; b < NCH; b++) { int t = g_bsum[b]; g_bsum[b] = run; run += t; }
        g_rowptr[NN] = EE;
    }
}

__global__ void csr_scan3_kernel() {
    __shared__ int sm[256];
    int tid = threadIdx.x;
    int i = blockIdx.x * 256 + tid;
    int cval = (i < NN) ? g_rowcnt[i] : 0;
    sm[tid] = cval;
    __syncthreads();
    for (int off = 1; off < 256; off <<= 1) {
        int t = (tid >= off) ? sm[tid - off] : 0;
        __syncthreads();
        sm[tid] += t;
        __syncthreads();
    }
    if (i < NN) g_rowptr[i] = g_bsum[blockIdx.x] + sm[tid] - cval;
}

__global__ void csr_scatter_kernel(const void* __restrict__ ei) {
    int e = blockIdx.x * blockDim.x + threadIdx.x;
    if (e >= EE) return;
    int mode = g_mode_ei;
    int src = clampi(ld_idx(ei, e, mode), NN);
    int dst = clampi(ld_idx(ei, EE + e, mode), NN);
    int pos = g_rowptr[dst] + atomicAdd(&g_fill[dst], 1);
    g_esrc[pos] = src;
}

// ---------------- SGEMM: g_h = X @ W (+cellW) --------------------------------
__global__ void __launch_bounds__(1024) gemm_kernel(
        const float* X, const float* __restrict__ W,
        const void* __restrict__ cids, int addCell) {
    __shared__ float sX[8][CC];
    int rloc = threadIdx.x >> 7;
    int c = threadIdx.x & 127;
    int row = blockIdx.x * 8 + rloc;

    sX[rloc][c] = X[row * CC + c];
    __syncthreads();

    float acc = 0.f;
#pragma unroll 8
    for (int k = 0; k < CC; k++)
        acc += sX[rloc][k] * W[k * CC + c];

    if (addCell) {
        int cid = clampi(ld_idx(cids, row, g_mode_cid), NUM_CELLS);
        acc += g_cellW[cid * CC + c];
    }
    g_h[row * CC + c] = acc;
}

// ---------------- alpha dot products per node --------------------------------
__global__ void asad_kernel(Vec8 v, int layer) {
    int gid = (blockIdx.x * blockDim.x + threadIdx.x) >> 5;
    int lane = threadIdx.x & 31;
    if (gid >= NN) return;

    const float* a_src = v.p[(layer == 1) ? g_r_as1 : g_r_as2];
    const float* a_dst = v.p[(layer == 1) ? g_r_ad1 : g_r_ad2];

    const float4* H4 = (const float4*)g_h;
    float4 hv = H4[gid * 32 + lane];
    float s0 = a_src[lane * 4 + 0], s1 = a_src[lane * 4 + 1];
    float s2 = a_src[lane * 4 + 2], s3 = a_src[lane * 4 + 3];
    float d0 = a_dst[lane * 4 + 0], d1 = a_dst[lane * 4 + 1];
    float d2 = a_dst[lane * 4 + 2], d3 = a_dst[lane * 4 + 3];

    float ps = hv.x * s0 + hv.y * s1 + hv.z * s2 + hv.w * s3;
    float pd = hv.x * d0 + hv.y * d1 + hv.z * d2 + hv.w * d3;
#pragma unroll
    for (int off = 16; off; off >>= 1) {
        ps += __shfl_xor_sync(FULL, ps, off);
        pd += __shfl_xor_sync(FULL, pd, off);
    }
    if (lane == 0) { g_as[gid] = ps; g_ad[gid] = pd; }
}

// ---------------- CSR aggregation + fused epilogue ---------------------------
// One warp per destination node. Gathers h[src] (L2-resident) with coalesced
// float4 loads, accumulates unnormalized softmax, then applies the layer
// epilogue in-warp. layer==1: /denom + b1, LN, ELU -> outbuf (x2).
// layer==2: /denom + b2 -> outbuf (final).
__global__ void agg_kernel(Vec8 v, int layer, float* outbuf) {
    int gid = (blockIdx.x * blockDim.x + threadIdx.x) >> 5;
    int lane = threadIdx.x & 31;
    if (gid >= NN) return;

    const float4* H4 = (const float4*)g_h;
    float ad_d = g_ad[gid];

    // self loop
    float es = g_as[gid] + ad_d;
    es = (es > 0.f) ? es : NEG_SLOPE * es;
    float exs = expf(es);
    float4 hv = H4[gid * 32 + lane];
    float4 acc = make_float4(exs * hv.x, exs * hv.y, exs * hv.z, exs * hv.w);
    float denp = 0.f;

    int begin = g_rowptr[gid];
    int end = g_rowptr[gid + 1];
    for (int base = begin; base < end; base += 32) {
        int j = base + lane;
        int srcj = 0;
        float ex = 0.f;
        if (j < end) {
            srcj = g_esrc[j];
            float e = g_as[srcj] + ad_d;
            e = (e > 0.f) ? e : NEG_SLOPE * e;
            ex = expf(e);
            denp += ex;
        }
        int cnt = end - base; if (cnt > 32) cnt = 32;
        for (int k = 0; k < cnt; k++) {
            int s = __shfl_sync(FULL, srcj, k);
            float exk = __shfl_sync(FULL, ex, k);
            float4 hs = H4[s * 32 + lane];
            acc.x += exk * hs.x;
            acc.y += exk * hs.y;
            acc.z += exk * hs.z;
            acc.w += exk * hs.w;
        }
    }
#pragma unroll
    for (int off = 16; off; off >>= 1)
        denp += __shfl_xor_sync(FULL, denp, off);
    float inv = 1.f / (denp + exs);

    if (layer == 1) {
        const float* b1   = v.p[g_r_b1];
        const float* ln_g = v.p[g_r_lng];
        const float* ln_b = v.p[g_r_lnb];
        float o0 = acc.x * inv + b1[lane * 4 + 0];
        float o1 = acc.y * inv + b1[lane * 4 + 1];
        float o2 = acc.z * inv + b1[lane * 4 + 2];
        float o3 = acc.w * inv + b1[lane * 4 + 3];

        float s = o0 + o1 + o2 + o3;
        float sq = o0 * o0 + o1 * o1 + o2 * o2 + o3 * o3;
#pragma unroll
        for (int off = 16; off; off >>= 1) {
            s  += __shfl_xor_sync(FULL, s, off);
            sq += __shfl_xor_sync(FULL, sq, off);
        }
        float mu = s * (1.f / CC);
        float var = sq * (1.f / CC) - mu * mu;
        float rstd = rsqrtf(var + LN_EPS);

        float y0 = (o0 - mu) * rstd * ln_g[lane * 4 + 0] + ln_b[lane * 4 + 0];
        float y1 = (o1 - mu) * rstd * ln_g[lane * 4 + 1] + ln_b[lane * 4 + 1];
        float y2 = (o2 - mu) * rstd * ln_g[lane * 4 + 2] + ln_b[lane * 4 + 2];
        float y3 = (o3 - mu) * rstd * ln_g[lane * 4 + 3] + ln_b[lane * 4 + 3];
        y0 = (y0 > 0.f) ? y0 : expm1f(y0);
        y1 = (y1 > 0.f) ? y1 : expm1f(y1);
        y2 = (y2 > 0.f) ? y2 : expm1f(y2);
        y3 = (y3 > 0.f) ? y3 : expm1f(y3);

        float* op = outbuf + gid * CC + lane * 4;
        op[0] = y0; op[1] = y1; op[2] = y2; op[3] = y3;
    } else {
        const float* b2 = v.p[g_r_b2];
        float* op = outbuf + gid * CC + lane * 4;
        op[0] = acc.x * inv + b2[lane * 4 + 0];
        op[1] = acc.y * inv + b2[lane * 4 + 1];
        op[2] = acc.z * inv + b2[lane * 4 + 2];
        op[3] = acc.w * inv + b2[lane * 4 + 3];
    }
}

// -----------------------------------------------------------------------------
extern "C" void kernel_launch(void* const* d_in, const int* in_sizes, int n_in,
                              void* d_out, int out_size) {
    // --- input remap by element count (verified: counts, dict order) ---
    int ix = 0, icid = 1, iei = 2, icemb = 3, iW1 = 4, iW2 = 10;
    int vecidx[8];
    int nvec = 0;
    {
        int fx = -1, fcid = -1, fei = -1, fcemb = -1, fW1 = -1, fW2 = -1;
        for (int i = 0; i < n_in; i++) {
            long long s = in_sizes[i];
            if (s == NN * CC) fx = (fx < 0) ? i : fx;
            else if (s == NN || s == 2 * NN) fcid = (fcid < 0) ? i : fcid;
            else if (s == 2LL * EE || s == 4LL * EE) fei = (fei < 0) ? i : fei;
            else if (s == NUM_CELLS * CE) fcemb = (fcemb < 0) ? i : fcemb;
            else if (s == (CC + CE) * CC) fW1 = (fW1 < 0) ? i : fW1;
            else if (s == CC * CC) fW2 = (fW2 < 0) ? i : fW2;
            else if (s == CC && nvec < 8) vecidx[nvec++] = i;
        }
        if (fx >= 0 && fcid >= 0 && fei >= 0 && fcemb >= 0 && fW1 >= 0 &&
            fW2 >= 0 && nvec == 8) {
            ix = fx; icid = fcid; iei = fei; icemb = fcemb; iW1 = fW1; iW2 = fW2;
        } else {
            ix = 0; icid = 1; iei = 2; icemb = 3; iW1 = 4; iW2 = 10;
            vecidx[0] = 5; vecidx[1] = 6; vecidx[2] = 7; vecidx[3] = 8;
            vecidx[4] = 9; vecidx[5] = 11; vecidx[6] = 12; vecidx[7] = 13;
        }
    }

    const float* x_base  = (const float*)d_in[ix];
    const void*  cids    = d_in[icid];
    const void*  ei      = d_in[iei];
    const float* cellemb = (const float*)d_in[icemb];
    const float* W1      = (const float*)d_in[iW1];
    const float* W2      = (const float*)d_in[iW2];
    Vec8 v;
    for (int j = 0; j < 8; j++) v.p[j] = (const float*)d_in[vecidx[j]];
    float* out = (float*)d_out;

    int gemm_blocks = NN / 8;
    int node_blocks = (NN * 32 + 255) / 256;
    int nn_blocks   = (NN + 255) / 256;
    int ee_blocks   = (EE + 255) / 256;

    detect_kernel<<<1, 256>>>(ei, 2 * EE, NN, 0);
    detect_kernel<<<1, 256>>>(cids, NN, NUM_CELLS, 1);
    classify_kernel<<<1, 256>>>(v);
    cellw_kernel<<<NUM_CELLS, CC>>>(cellemb, W1);

    // ---- CSR build (once; reused by both layers) ----
    csr_zero_kernel<<<nn_blocks, 256>>>();
    csr_hist_kernel<<<ee_blocks, 256>>>(ei);
    csr_scan1_kernel<<<NCH, 256>>>();
    csr_scan2_kernel<<<1, 32>>>();
    csr_scan3_kernel<<<NCH, 256>>>();
    csr_scatter_kernel<<<ee_blocks, 256>>>(ei);

    // ---- layer 1: gemm -> as/ad -> aggregate (x2 into d_out) ----
    gemm_kernel<<<gemm_blocks, 1024>>>(x_base, W1, cids, 1);
    asad_kernel<<<node_blocks, 256>>>(v, 1);
    agg_kernel<<<node_blocks, 256>>>(v, 1, out);

    // ---- layer 2: gemm reads x2 from d_out -> as/ad -> aggregate (final) ----
    gemm_kernel<<<gemm_blocks, 1024>>>(out, W2, cids, 0);
    asad_kernel<<<node_blocks, 256>>>(v, 2);
    agg_kernel<<<node_blocks, 256>>>(v, 2, out);
}

// round 10
// speedup vs baseline: 2.2020x; 1.8206x over previous
#include <cuda_runtime.h>

#define NN 50000
#define EE 600000
#define CC 128
#define CE 8
#define NUM_CELLS 854
#define NEG_SLOPE 0.2f
#define LN_EPS 1e-5f
#define NCH 196            // ceil(NN/256)
#define FULL 0xffffffffu

struct Vec8 { const float* p[8]; };

// ------- scratch: __device__ symbols, referenced ONLY inside device code -----
__device__ __align__(16) float g_h[NN * CC];
__device__ __align__(16) float g_cellW[NUM_CELLS * CC];
__device__ float g_as[NN];
__device__ float g_ad[NN];
__device__ int g_rowptr[NN + 1];
__device__ int g_rowcnt[NN];
__device__ int g_fill[NN];
__device__ int g_bsum[NCH];
__device__ int g_esrc[EE];
__device__ int g_mode_ei;      // 0=int32 1=int64 2=float32
__device__ int g_mode_cid;
__device__ int g_r_as1, g_r_ad1, g_r_as2, g_r_ad2;
__device__ int g_r_b1, g_r_lng, g_r_lnb, g_r_b2;

// ---------------- index dtype detection --------------------------------------
__global__ void detect_kernel(const void* buf, int n, int maxval, int which) {
    __shared__ int ok64, ok32, okf;
    if (threadIdx.x == 0) { ok64 = 1; ok32 = 1; okf = 1; }
    __syncthreads();
    const long long* p64 = (const long long*)buf;
    const int* p32 = (const int*)buf;
    const float* pf = (const float*)buf;
    int half = n / 2;
    int stride = half / 1024; if (stride < 1) stride = 1;
    int b64 = 1, b32 = 1, bf = 1;
    for (int i = threadIdx.x; i < 1024; i += blockDim.x) {
        int idx = i * stride; if (idx >= half) idx = half - 1;
        long long v64 = p64[idx];
        int v32 = p32[idx];
        float vf = pf[idx];
        b64 &= (v64 >= 0 && v64 < maxval);
        b32 &= (v32 >= 0 && v32 < maxval);
        bf  &= (isfinite(vf) && vf >= 0.f && vf < (float)maxval &&
                vf == rintf(vf));
    }
    if (!b64) atomicAnd(&ok64, 0);
    if (!b32) atomicAnd(&ok32, 0);
    if (!bf)  atomicAnd(&okf, 0);
    __syncthreads();
    if (threadIdx.x == 0) {
        int m = ok64 ? 1 : (ok32 ? 0 : (okf ? 2 : 0));
        if (which == 0) g_mode_ei = m; else g_mode_cid = m;
    }
}

__device__ __forceinline__ int ld_idx(const void* p, int i, int mode) {
    if (mode == 1) return (int)((const long long*)p)[i];
    if (mode == 2) return (int)((const float*)p)[i];
    return ((const int*)p)[i];
}

__device__ __forceinline__ int clampi(int v, int hi) {
    v = (v < 0) ? 0 : v;
    return (v >= hi) ? hi - 1 : v;
}

// ---------------- classify the eight CC-length vectors -----------------------
__global__ void classify_kernel(Vec8 v) {
    __shared__ int isZ[8], isO[8];
    int t = threadIdx.x;
    int vec = t >> 5, lane = t & 31;
    if (vec < 8) {
        const float* pv = v.p[vec];
        int z = 1, o = 1;
        for (int i = lane; i < CC; i += 32) {
            float x = pv[i];
            z &= (x == 0.0f);
            o &= (x == 1.0f);
        }
#pragma unroll
        for (int off = 16; off; off >>= 1) {
            z &= __shfl_xor_sync(FULL, z, off);
            o &= __shfl_xor_sync(FULL, o, off);
        }
        if (lane == 0) { isZ[vec] = z; isO[vec] = o; }
    }
    __syncthreads();
    if (t == 0) {
        int zm = 0, om = 0;
        for (int i = 0; i < 8; i++) { zm |= isZ[i] << i; om |= isO[i] << i; }
        int as1 = 0, ad1 = 1, b1 = 2, lng = 3, lnb = 4, as2 = 5, ad2 = 6, b2 = 7;
        if (zm == 0x70 && om == 0x80) {          // alphabetical
            ad1 = 0; ad2 = 1; as1 = 2; as2 = 3; b1 = 4; b2 = 5; lnb = 6; lng = 7;
        } else if (zm == 0x29 && om == 0x10) {   // reversed dict
            b2 = 0; ad2 = 1; as2 = 2; lnb = 3; lng = 4; b1 = 5; ad1 = 6; as1 = 7;
        } else if (zm == 0x0E && om == 0x01) {   // reversed alphabetical
            lng = 0; lnb = 1; b2 = 2; b1 = 3; as2 = 4; as1 = 5; ad2 = 6; ad1 = 7;
        }
        g_r_as1 = as1; g_r_ad1 = ad1; g_r_as2 = as2; g_r_ad2 = ad2;
        g_r_b1 = b1; g_r_lng = lng; g_r_lnb = lnb; g_r_b2 = b2;
    }
}

// ---------------- cell embedding folded into W1 ------------------------------
__global__ void cellw_kernel(const float* __restrict__ cell_emb,
                             const float* __restrict__ W1) {
    int cell = blockIdx.x;
    int c = threadIdx.x;
    float acc = 0.f;
#pragma unroll
    for (int j = 0; j < CE; j++)
        acc += cell_emb[cell * CE + j] * W1[(CC + j) * CC + c];
    g_cellW[cell * CC + c] = acc;
}

// ---------------- CSR build --------------------------------------------------
__global__ void csr_zero_kernel() {
    int i = blockIdx.x * blockDim.x + threadIdx.x;
    if (i < NN) { g_rowcnt[i] = 0; g_fill[i] = 0; }
}

__global__ void csr_hist_kernel(const void* __restrict__ ei) {
    int e = blockIdx.x * blockDim.x + threadIdx.x;
    if (e >= EE) return;
    int dst = clampi(ld_idx(ei, EE + e, g_mode_ei), NN);
    atomicAdd(&g_rowcnt[dst], 1);
}

__global__ void csr_scan1_kernel() {
    __shared__ int sm[256];
    int i = blockIdx.x * 256 + threadIdx.x;
    sm[threadIdx.x] = (i < NN) ? g_rowcnt[i] : 0;
    __syncthreads();
    for (int s = 128; s; s >>= 1) {
        if (threadIdx.x < s) sm[threadIdx.x] += sm[threadIdx.x + s];
        __syncthreads();
    }
    if (threadIdx.x == 0) g_bsum[blockIdx.x] = sm[0];
}

__global__ void csr_scan2_kernel() {
    if (threadIdx.x == 0) {
        int run = 0;
        for (int b = 0; b < NCH; b++) { int t = g_bsum[b]; g_bsum[b] = run; run += t; }
        g_rowptr[NN] = EE;
    }
}

__global__ void csr_scan3_kernel() {
    __shared__ int sm[256];
    int tid = threadIdx.x;
    int i = blockIdx.x * 256 + tid;
    int cval = (i < NN) ? g_rowcnt[i] : 0;
    sm[tid] = cval;
    __syncthreads();
    for (int off = 1; off < 256; off <<= 1) {
        int t = (tid >= off) ? sm[tid - off] : 0;
        __syncthreads();
        sm[tid] += t;
        __syncthreads();
    }
    if (i < NN) g_rowptr[i] = g_bsum[blockIdx.x] + sm[tid] - cval;
}

__global__ void csr_scatter_kernel(const void* __restrict__ ei) {
    int e = blockIdx.x * blockDim.x + threadIdx.x;
    if (e >= EE) return;
    int mode = g_mode_ei;
    int src = clampi(ld_idx(ei, e, mode), NN);
    int dst = clampi(ld_idx(ei, EE + e, mode), NN);
    int pos = g_rowptr[dst] + atomicAdd(&g_fill[dst], 1);
    g_esrc[pos] = src;
}

// ---------------- tiled SGEMM + fused alpha dots -----------------------------
// 256 threads, 64-row x 128-col tile, K chunked by 32. Thread (cg=tid&31,
// rg=tid>>5) owns cols [4cg,4cg+4) of rows rg*8..rg*8+7 -> warp rg owns 8
// complete rows, so as/ad = warp reductions in the epilogue (asad pass fused).
__global__ void __launch_bounds__(256) gemm_kernel(
        const float* __restrict__ X, const float* __restrict__ W,
        const void* __restrict__ cids, Vec8 v, int layer) {
    __shared__ float4 sW4[32 * 32];   // [k_local 0..31][colgrp 0..31]
    __shared__ float4 sX4[64 * 8];    // [row_local 0..63][kgrp 0..7]

    int tid = threadIdx.x;
    int rowBase = blockIdx.x * 64;
    int cg = tid & 31;
    int rg = tid >> 5;

    const float4* W4 = (const float4*)W;   // first 128 rows row-major
    const float4* X4 = (const float4*)X;

    float4 acc[8];
#pragma unroll
    for (int r = 0; r < 8; r++) acc[r] = make_float4(0.f, 0.f, 0.f, 0.f);

    for (int kc = 0; kc < 4; kc++) {
        for (int i = tid; i < 1024; i += 256)
            sW4[i] = W4[(kc * 32 + (i >> 5)) * 32 + (i & 31)];
        for (int i = tid; i < 512; i += 256) {
            int r = rowBase + (i >> 3);
            int rr = (r < NN) ? r : NN - 1;
            sX4[i] = X4[rr * 32 + kc * 8 + (i & 7)];
        }
        __syncthreads();

#pragma unroll
        for (int k4 = 0; k4 < 8; k4++) {
            float4 xv[8];
#pragma unroll
            for (int r = 0; r < 8; r++)
                xv[r] = sX4[(rg * 8 + r) * 8 + k4];
#pragma unroll
            for (int kk = 0; kk < 4; kk++) {
                float4 w = sW4[(k4 * 4 + kk) * 32 + cg];
#pragma unroll
                for (int r = 0; r < 8; r++) {
                    float xs = (kk == 0) ? xv[r].x : (kk == 1) ? xv[r].y
                              : (kk == 2) ? xv[r].z : xv[r].w;
                    acc[r].x += xs * w.x;
                    acc[r].y += xs * w.y;
                    acc[r].z += xs * w.z;
                    acc[r].w += xs * w.w;
                }
            }
        }
        __syncthreads();
    }

    // epilogue: +cellW (layer 1), store h, fused as/ad warp reductions
    const float* a_src = v.p[(layer == 1) ? g_r_as1 : g_r_as2];
    const float* a_dst = v.p[(layer == 1) ? g_r_ad1 : g_r_ad2];
    float s0 = a_src[cg * 4 + 0], s1 = a_src[cg * 4 + 1];
    float s2 = a_src[cg * 4 + 2], s3 = a_src[cg * 4 + 3];
    float d0 = a_dst[cg * 4 + 0], d1 = a_dst[cg * 4 + 1];
    float d2 = a_dst[cg * 4 + 2], d3 = a_dst[cg * 4 + 3];

    const float4* cellW4 = (const float4*)g_cellW;
    float4* H4 = (float4*)g_h;
#pragma unroll
    for (int r = 0; r < 8; r++) {
        int row = rowBase + rg * 8 + r;
        if (row >= NN) continue;    // uniform across the warp (row indep of cg)
        float4 a = acc[r];
        if (layer == 1) {
            int cid = clampi(ld_idx(cids, row, g_mode_cid), NUM_CELLS);
            float4 cw = cellW4[cid * 32 + cg];
            a.x += cw.x; a.y += cw.y; a.z += cw.z; a.w += cw.w;
        }
        H4[row * 32 + cg] = a;
        float ps = a.x * s0 + a.y * s1 + a.z * s2 + a.w * s3;
        float pd = a.x * d0 + a.y * d1 + a.z * d2 + a.w * d3;
#pragma unroll
        for (int off = 16; off; off >>= 1) {
            ps += __shfl_xor_sync(FULL, ps, off);
            pd += __shfl_xor_sync(FULL, pd, off);
        }
        if (cg == 0) { g_as[row] = ps; g_ad[row] = pd; }
    }
}

// ---------------- CSR aggregation + fused epilogue ---------------------------
__global__ void agg_kernel(Vec8 v, int layer, float* outbuf) {
    int gid = (blockIdx.x * blockDim.x + threadIdx.x) >> 5;
    int lane = threadIdx.x & 31;
    if (gid >= NN) return;

    const float4* H4 = (const float4*)g_h;
    float ad_d = g_ad[gid];

    // self loop
    float es = g_as[gid] + ad_d;
    es = (es > 0.f) ? es : NEG_SLOPE * es;
    float exs = expf(es);
    float4 hv = H4[gid * 32 + lane];
    float4 acc = make_float4(exs * hv.x, exs * hv.y, exs * hv.z, exs * hv.w);
    float denp = 0.f;

    int begin = g_rowptr[gid];
    int end = g_rowptr[gid + 1];
    for (int base = begin; base < end; base += 32) {
        int j = base + lane;
        int srcj = 0;
        float ex = 0.f;
        if (j < end) {
            srcj = g_esrc[j];
            float e = g_as[srcj] + ad_d;
            e = (e > 0.f) ? e : NEG_SLOPE * e;
            ex = expf(e);
            denp += ex;
        }
        int cnt = end - base; if (cnt > 32) cnt = 32;
        for (int k = 0; k < cnt; k++) {
            int s = __shfl_sync(FULL, srcj, k);
            float exk = __shfl_sync(FULL, ex, k);
            float4 hs = H4[s * 32 + lane];
            acc.x += exk * hs.x;
            acc.y += exk * hs.y;
            acc.z += exk * hs.z;
            acc.w += exk * hs.w;
        }
    }
#pragma unroll
    for (int off = 16; off; off >>= 1)
        denp += __shfl_xor_sync(FULL, denp, off);
    float inv = 1.f / (denp + exs);

    if (layer == 1) {
        const float* b1   = v.p[g_r_b1];
        const float* ln_g = v.p[g_r_lng];
        const float* ln_b = v.p[g_r_lnb];
        float o0 = acc.x * inv + b1[lane * 4 + 0];
        float o1 = acc.y * inv + b1[lane * 4 + 1];
        float o2 = acc.z * inv + b1[lane * 4 + 2];
        float o3 = acc.w * inv + b1[lane * 4 + 3];

        float s = o0 + o1 + o2 + o3;
        float sq = o0 * o0 + o1 * o1 + o2 * o2 + o3 * o3;
#pragma unroll
        for (int off = 16; off; off >>= 1) {
            s  += __shfl_xor_sync(FULL, s, off);
            sq += __shfl_xor_sync(FULL, sq, off);
        }
        float mu = s * (1.f / CC);
        float var = sq * (1.f / CC) - mu * mu;
        float rstd = rsqrtf(var + LN_EPS);

        float y0 = (o0 - mu) * rstd * ln_g[lane * 4 + 0] + ln_b[lane * 4 + 0];
        float y1 = (o1 - mu) * rstd * ln_g[lane * 4 + 1] + ln_b[lane * 4 + 1];
        float y2 = (o2 - mu) * rstd * ln_g[lane * 4 + 2] + ln_b[lane * 4 + 2];
        float y3 = (o3 - mu) * rstd * ln_g[lane * 4 + 3] + ln_b[lane * 4 + 3];
        y0 = (y0 > 0.f) ? y0 : expm1f(y0);
        y1 = (y1 > 0.f) ? y1 : expm1f(y1);
        y2 = (y2 > 0.f) ? y2 : expm1f(y2);
        y3 = (y3 > 0.f) ? y3 : expm1f(y3);

        float* op = outbuf + gid * CC + lane * 4;
        op[0] = y0; op[1] = y1; op[2] = y2; op[3] = y3;
    } else {
        const float* b2 = v.p[g_r_b2];
        float* op = outbuf + gid * CC + lane * 4;
        op[0] = acc.x * inv + b2[lane * 4 + 0];
        op[1] = acc.y * inv + b2[lane * 4 + 1];
        op[2] = acc.z * inv + b2[lane * 4 + 2];
        op[3] = acc.w * inv + b2[lane * 4 + 3];
    }
}

// -----------------------------------------------------------------------------
extern "C" void kernel_launch(void* const* d_in, const int* in_sizes, int n_in,
                              void* d_out, int out_size) {
    // --- input remap by element count (verified: counts, dict order) ---
    int ix = 0, icid = 1, iei = 2, icemb = 3, iW1 = 4, iW2 = 10;
    int vecidx[8];
    int nvec = 0;
    {
        int fx = -1, fcid = -1, fei = -1, fcemb = -1, fW1 = -1, fW2 = -1;
        for (int i = 0; i < n_in; i++) {
            long long s = in_sizes[i];
            if (s == NN * CC) fx = (fx < 0) ? i : fx;
            else if (s == NN || s == 2 * NN) fcid = (fcid < 0) ? i : fcid;
            else if (s == 2LL * EE || s == 4LL * EE) fei = (fei < 0) ? i : fei;
            else if (s == NUM_CELLS * CE) fcemb = (fcemb < 0) ? i : fcemb;
            else if (s == (CC + CE) * CC) fW1 = (fW1 < 0) ? i : fW1;
            else if (s == CC * CC) fW2 = (fW2 < 0) ? i : fW2;
            else if (s == CC && nvec < 8) vecidx[nvec++] = i;
        }
        if (fx >= 0 && fcid >= 0 && fei >= 0 && fcemb >= 0 && fW1 >= 0 &&
            fW2 >= 0 && nvec == 8) {
            ix = fx; icid = fcid; iei = fei; icemb = fcemb; iW1 = fW1; iW2 = fW2;
        } else {
            ix = 0; icid = 1; iei = 2; icemb = 3; iW1 = 4; iW2 = 10;
            vecidx[0] = 5; vecidx[1] = 6; vecidx[2] = 7; vecidx[3] = 8;
            vecidx[4] = 9; vecidx[5] = 11; vecidx[6] = 12; vecidx[7] = 13;
        }
    }

    const float* x_base  = (const float*)d_in[ix];
    const void*  cids    = d_in[icid];
    const void*  ei      = d_in[iei];
    const float* cellemb = (const float*)d_in[icemb];
    const float* W1      = (const float*)d_in[iW1];
    const float* W2      = (const float*)d_in[iW2];
    Vec8 v;
    for (int j = 0; j < 8; j++) v.p[j] = (const float*)d_in[vecidx[j]];
    float* out = (float*)d_out;

    int gemm_blocks = (NN + 63) / 64;
    int node_blocks = (NN * 32 + 255) / 256;
    int nn_blocks   = (NN + 255) / 256;
    int ee_blocks   = (EE + 255) / 256;

    detect_kernel<<<1, 256>>>(ei, 2 * EE, NN, 0);
    detect_kernel<<<1, 256>>>(cids, NN, NUM_CELLS, 1);
    classify_kernel<<<1, 256>>>(v);
    cellw_kernel<<<NUM_CELLS, CC>>>(cellemb, W1);

    // ---- CSR build (once; reused by both layers) ----
    csr_zero_kernel<<<nn_blocks, 256>>>();
    csr_hist_kernel<<<ee_blocks, 256>>>(ei);
    csr_scan1_kernel<<<NCH, 256>>>();
    csr_scan2_kernel<<<1, 32>>>();
    csr_scan3_kernel<<<NCH, 256>>>();
    csr_scatter_kernel<<<ee_blocks, 256>>>(ei);

    // ---- layer 1: gemm(+asad) -> aggregate (x2 into d_out) ----
    gemm_kernel<<<gemm_blocks, 256>>>(x_base, W1, cids, v, 1);
    agg_kernel<<<node_blocks, 256>>>(v, 1, out);

    // ---- layer 2: gemm(+asad) reads x2 from d_out -> aggregate (final) ----
    gemm_kernel<<<gemm_blocks, 256>>>(out, W2, cids, v, 2);
    agg_kernel<<<node_blocks, 256>>>(v, 2, out);
}

// round 11
// speedup vs baseline: 2.4732x; 1.1232x over previous
#include <cuda_runtime.h>
#include <cstdint>

#define NN 50000
#define EE 600000
#define CC 128
#define CE 8
#define NUM_CELLS 854
#define NEG_SLOPE 0.2f
#define LN_EPS 1e-5f
#define NCH 196            // ceil(NN/256)
#define FULL 0xffffffffu

struct Vec8 { const float* p[8]; };

// ------- scratch: __device__ symbols, referenced ONLY inside device code -----
__device__ __align__(16) float g_h[NN * CC];
__device__ __align__(16) float g_cellW[NUM_CELLS * CC];
__device__ float g_as[NN];
__device__ float g_ad[NN];
__device__ int g_rowptr[NN + 1];
__device__ int g_rowcnt[NN];
__device__ int g_fill[NN];
__device__ int g_bsum[NCH];
__device__ int g_esrc[EE];
__device__ int g_mode_ei;      // 0=int32 1=int64 2=float32
__device__ int g_mode_cid;
__device__ int g_r_as1, g_r_ad1, g_r_as2, g_r_ad2;
__device__ int g_r_b1, g_r_lng, g_r_lnb, g_r_b2;

// ---------------- helpers -----------------------------------------------------
__device__ __forceinline__ int ld_idx(const void* p, int i, int mode) {
    if (mode == 1) return (int)((const long long*)p)[i];
    if (mode == 2) return (int)((const float*)p)[i];
    return ((const int*)p)[i];
}

__device__ __forceinline__ int clampi(int v, int hi) {
    v = (v < 0) ? 0 : v;
    return (v >= hi) ? hi - 1 : v;
}

// split fp32 into tf32 hi + residual lo (lo passed raw; HW truncation of lo
// contributes ~1e-7 relative — negligible)
__device__ __forceinline__ void split_tf32(float x, uint32_t& hi, uint32_t& lo) {
    uint32_t h;
    asm("cvt.rna.tf32.f32 %0, %1;" : "=r"(h) : "f"(x));
    hi = h;
    lo = __float_as_uint(x - __uint_as_float(h));
}

__device__ __forceinline__ void mma_tf32(float* d, const uint32_t* a,
                                         uint32_t b0, uint32_t b1) {
    asm volatile(
        "mma.sync.aligned.m16n8k8.row.col.f32.tf32.tf32.f32 "
        "{%0,%1,%2,%3}, {%4,%5,%6,%7}, {%8,%9}, {%0,%1,%2,%3};"
        : "+f"(d[0]), "+f"(d[1]), "+f"(d[2]), "+f"(d[3])
        : "r"(a[0]), "r"(a[1]), "r"(a[2]), "r"(a[3]), "r"(b0), "r"(b1));
}

// ---------------- prep: dtype detection (blocks 0,1) + classify (block 2) ----
__global__ void prep_kernel(const void* ei, const void* cids, Vec8 v) {
    int task = blockIdx.x;
    if (task < 2) {
        __shared__ int ok64, ok32, okf;
        if (threadIdx.x == 0) { ok64 = 1; ok32 = 1; okf = 1; }
        __syncthreads();
        const void* buf = (task == 0) ? ei : cids;
        int n = (task == 0) ? 2 * EE : NN;
        int maxval = (task == 0) ? NN : NUM_CELLS;
        const long long* p64 = (const long long*)buf;
        const int* p32 = (const int*)buf;
        const float* pf = (const float*)buf;
        int half = n / 2;
        int stride = half / 1024; if (stride < 1) stride = 1;
        int b64 = 1, b32 = 1, bf = 1;
        for (int i = threadIdx.x; i < 1024; i += blockDim.x) {
            int idx = i * stride; if (idx >= half) idx = half - 1;
            long long v64 = p64[idx];
            int v32 = p32[idx];
            float vf = pf[idx];
            b64 &= (v64 >= 0 && v64 < maxval);
            b32 &= (v32 >= 0 && v32 < maxval);
            bf  &= (isfinite(vf) && vf >= 0.f && vf < (float)maxval &&
                    vf == rintf(vf));
        }
        if (!b64) atomicAnd(&ok64, 0);
        if (!b32) atomicAnd(&ok32, 0);
        if (!bf)  atomicAnd(&okf, 0);
        __syncthreads();
        if (threadIdx.x == 0) {
            int m = ok64 ? 1 : (ok32 ? 0 : (okf ? 2 : 0));
            if (task == 0) g_mode_ei = m; else g_mode_cid = m;
        }
        return;
    }
    // task 2: classify the eight CC-length vectors
    __shared__ int isZ[8], isO[8];
    int t = threadIdx.x;
    int vec = t >> 5, lane = t & 31;
    if (vec < 8) {
        const float* pv = v.p[vec];
        int z = 1, o = 1;
        for (int i = lane; i < CC; i += 32) {
            float x = pv[i];
            z &= (x == 0.0f);
            o &= (x == 1.0f);
        }
#pragma unroll
        for (int off = 16; off; off >>= 1) {
            z &= __shfl_xor_sync(FULL, z, off);
            o &= __shfl_xor_sync(FULL, o, off);
        }
        if (lane == 0) { isZ[vec] = z; isO[vec] = o; }
    }
    __syncthreads();
    if (t == 0) {
        int zm = 0, om = 0;
        for (int i = 0; i < 8; i++) { zm |= isZ[i] << i; om |= isO[i] << i; }
        int as1 = 0, ad1 = 1, b1 = 2, lng = 3, lnb = 4, as2 = 5, ad2 = 6, b2 = 7;
        if (zm == 0x70 && om == 0x80) {          // alphabetical
            ad1 = 0; ad2 = 1; as1 = 2; as2 = 3; b1 = 4; b2 = 5; lnb = 6; lng = 7;
        } else if (zm == 0x29 && om == 0x10) {   // reversed dict
            b2 = 0; ad2 = 1; as2 = 2; lnb = 3; lng = 4; b1 = 5; ad1 = 6; as1 = 7;
        } else if (zm == 0x0E && om == 0x01) {   // reversed alphabetical
            lng = 0; lnb = 1; b2 = 2; b1 = 3; as2 = 4; as1 = 5; ad2 = 6; ad1 = 7;
        }
        g_r_as1 = as1; g_r_ad1 = ad1; g_r_as2 = as2; g_r_ad2 = ad2;
        g_r_b1 = b1; g_r_lng = lng; g_r_lnb = lnb; g_r_b2 = b2;
    }
}

// ---------------- cell embedding folded into W1 ------------------------------
__global__ void cellw_kernel(const float* __restrict__ cell_emb,
                             const float* __restrict__ W1) {
    int cell = blockIdx.x;
    int c = threadIdx.x;
    float acc = 0.f;
#pragma unroll
    for (int j = 0; j < CE; j++)
        acc += cell_emb[cell * CE + j] * W1[(CC + j) * CC + c];
    g_cellW[cell * CC + c] = acc;
}

// ---------------- CSR build --------------------------------------------------
__global__ void csr_zero_kernel() {
    int i = blockIdx.x * blockDim.x + threadIdx.x;
    if (i < NN) { g_rowcnt[i] = 0; g_fill[i] = 0; }
}

__global__ void csr_hist_kernel(const void* __restrict__ ei) {
    int e = blockIdx.x * blockDim.x + threadIdx.x;
    if (e >= EE) return;
    int dst = clampi(ld_idx(ei, EE + e, g_mode_ei), NN);
    atomicAdd(&g_rowcnt[dst], 1);
}

__global__ void csr_scan1_kernel() {
    __shared__ int sm[256];
    int i = blockIdx.x * 256 + threadIdx.x;
    sm[threadIdx.x] = (i < NN) ? g_rowcnt[i] : 0;
    __syncthreads();
    for (int s = 128; s; s >>= 1) {
        if (threadIdx.x < s) sm[threadIdx.x] += sm[threadIdx.x + s];
        __syncthreads();
    }
    if (threadIdx.x == 0) g_bsum[blockIdx.x] = sm[0];
}

__global__ void csr_scan2_kernel() {
    if (threadIdx.x == 0) {
        int run = 0;
        for (int b = 0; b < NCH; b++) { int t = g_bsum[b]; g_bsum[b] = run; run += t; }
        g_rowptr[NN] = EE;
    }
}

__global__ void csr_scan3_kernel() {
    __shared__ int sm[256];
    int tid = threadIdx.x;
    int i = blockIdx.x * 256 + tid;
    int cval = (i < NN) ? g_rowcnt[i] : 0;
    sm[tid] = cval;
    __syncthreads();
    for (int off = 1; off < 256; off <<= 1) {
        int t = (tid >= off) ? sm[tid - off] : 0;
        __syncthreads();
        sm[tid] += t;
        __syncthreads();
    }
    if (i < NN) g_rowptr[i] = g_bsum[blockIdx.x] + sm[tid] - cval;
}

__global__ void csr_scatter_kernel(const void* __restrict__ ei) {
    int e = blockIdx.x * blockDim.x + threadIdx.x;
    if (e >= EE) return;
    int mode = g_mode_ei;
    int src = clampi(ld_idx(ei, e, mode), NN);
    int dst = clampi(ld_idx(ei, EE + e, mode), NN);
    int pos = g_rowptr[dst] + atomicAdd(&g_fill[dst], 1);
    g_esrc[pos] = src;
}

// ---------------- tensor-core 3xTF32 GEMM + fused alpha dots -----------------
// Block: 256 threads = 8 warps in 4x2; 64-row x 128-col tile; K chunked by 32.
// Warp (wm=wid&3, wn=wid>>2) computes rows [16wm,16wm+16) x cols [64wn,64wn+64)
// via 8 m16n8k8 tiles. fp32 emulated as hi*hi + hi*lo + lo*hi (3 mmas).
__global__ void __launch_bounds__(256) gemm_kernel(
        const float* __restrict__ X, const float* __restrict__ W,
        const void* __restrict__ cids, Vec8 v, int layer) {
    __shared__ float sX[64 * 36];     // stride 36: conflict-free A frags
    __shared__ float sW[32 * 132];    // stride 132: conflict-free B frags
    __shared__ float sAS[CC], sAD[CC];
    __shared__ float sPS[64], sPD[64];

    int tid = threadIdx.x;
    int rowBase = blockIdx.x * 64;
    int lane = tid & 31, wid = tid >> 5;
    int wm = wid & 3, wn = wid >> 2;
    int g = lane >> 2, tig = lane & 3;

    const float* a_src = v.p[(layer == 1) ? g_r_as1 : g_r_as2];
    const float* a_dst = v.p[(layer == 1) ? g_r_ad1 : g_r_ad2];
    if (tid < CC) { sAS[tid] = a_src[tid]; sAD[tid] = a_dst[tid]; }

    float acc[8][4];
#pragma unroll
    for (int t = 0; t < 8; t++)
#pragma unroll
        for (int c = 0; c < 4; c++) acc[t][c] = 0.f;

    const float4* X4 = (const float4*)X;
    const float4* W4 = (const float4*)W;

    for (int kc = 0; kc < 4; kc++) {
        // stage X rows [rowBase,+64), k [32kc,+32)
        for (int i = tid; i < 512; i += 256) {
            int r = i >> 3, j = i & 7;
            int rr = rowBase + r; if (rr >= NN) rr = NN - 1;
            float4 t4 = X4[rr * 32 + kc * 8 + j];
            *(float4*)&sX[r * 36 + j * 4] = t4;
        }
        // stage W rows [32kc,+32), all 128 cols
        for (int i = tid; i < 1024; i += 256) {
            int k = i >> 5, j = i & 31;
            float4 t4 = W4[(kc * 32 + k) * 32 + j];
            *(float4*)&sW[k * 132 + j * 4] = t4;
        }
        __syncthreads();

#pragma unroll
        for (int k8 = 0; k8 < 4; k8++) {
            int kk = k8 * 8;
            uint32_t ah[4], al[4];
            int ar = wm * 16 + g;
            split_tf32(sX[ar * 36 + kk + tig],           ah[0], al[0]);
            split_tf32(sX[(ar + 8) * 36 + kk + tig],     ah[1], al[1]);
            split_tf32(sX[ar * 36 + kk + tig + 4],       ah[2], al[2]);
            split_tf32(sX[(ar + 8) * 36 + kk + tig + 4], ah[3], al[3]);
#pragma unroll
            for (int t = 0; t < 8; t++) {
                int n = wn * 64 + t * 8 + g;
                uint32_t bh0, bl0, bh1, bl1;
                split_tf32(sW[(kk + tig) * 132 + n],     bh0, bl0);
                split_tf32(sW[(kk + tig + 4) * 132 + n], bh1, bl1);
                mma_tf32(acc[t], ah, bh0, bh1);
                mma_tf32(acc[t], ah, bl0, bl1);
                mma_tf32(acc[t], al, bh0, bh1);
            }
        }
        __syncthreads();
    }

    // ---- epilogue: +cellW (layer1), store h, fused as/ad reductions ----
    int row0 = rowBase + wm * 16 + g;
    int row1 = row0 + 8;
    int cid0 = 0, cid1 = 0;
    if (layer == 1) {
        int lr0 = (row0 < NN) ? row0 : NN - 1;
        int lr1 = (row1 < NN) ? row1 : NN - 1;
        cid0 = clampi(ld_idx(cids, lr0, g_mode_cid), NUM_CELLS);
        cid1 = clampi(ld_idx(cids, lr1, g_mode_cid), NUM_CELLS);
    }
    float ps0 = 0.f, pd0 = 0.f, ps1 = 0.f, pd1 = 0.f;
#pragma unroll
    for (int t = 0; t < 8; t++) {
        int col = wn * 64 + t * 8 + 2 * tig;
        float h00 = acc[t][0], h01 = acc[t][1];
        float h10 = acc[t][2], h11 = acc[t][3];
        if (layer == 1) {
            h00 += g_cellW[cid0 * CC + col];
            h01 += g_cellW[cid0 * CC + col + 1];
            h10 += g_cellW[cid1 * CC + col];
            h11 += g_cellW[cid1 * CC + col + 1];
        }
        if (row0 < NN) *(float2*)&g_h[row0 * CC + col] = make_float2(h00, h01);
        if (row1 < NN) *(float2*)&g_h[row1 * CC + col] = make_float2(h10, h11);
        ps0 += h00 * sAS[col] + h01 * sAS[col + 1];
        pd0 += h00 * sAD[col] + h01 * sAD[col + 1];
        ps1 += h10 * sAS[col] + h11 * sAS[col + 1];
        pd1 += h10 * sAD[col] + h11 * sAD[col + 1];
    }
    // quad reduce (lanes 4g..4g+3 share the row)
    ps0 += __shfl_xor_sync(FULL, ps0, 1); ps0 += __shfl_xor_sync(FULL, ps0, 2);
    pd0 += __shfl_xor_sync(FULL, pd0, 1); pd0 += __shfl_xor_sync(FULL, pd0, 2);
    ps1 += __shfl_xor_sync(FULL, ps1, 1); ps1 += __shfl_xor_sync(FULL, ps1, 2);
    pd1 += __shfl_xor_sync(FULL, pd1, 1); pd1 += __shfl_xor_sync(FULL, pd1, 2);

    int lrow = wm * 16 + g;
    if (wn == 0 && tig == 0) {
        sPS[lrow] = ps0; sPD[lrow] = pd0;
        sPS[lrow + 8] = ps1; sPD[lrow + 8] = pd1;
    }
    __syncthreads();
    if (wn == 1 && tig == 0) {
        if (row0 < NN) { g_as[row0] = ps0 + sPS[lrow];     g_ad[row0] = pd0 + sPD[lrow]; }
        if (row1 < NN) { g_as[row1] = ps1 + sPS[lrow + 8]; g_ad[row1] = pd1 + sPD[lrow + 8]; }
    }
}

// ---------------- CSR aggregation + fused epilogue ---------------------------
__global__ void agg_kernel(Vec8 v, int layer, float* outbuf) {
    int gid = (blockIdx.x * blockDim.x + threadIdx.x) >> 5;
    int lane = threadIdx.x & 31;
    if (gid >= NN) return;

    const float4* H4 = (const float4*)g_h;
    float ad_d = g_ad[gid];

    // self loop
    float es = g_as[gid] + ad_d;
    es = (es > 0.f) ? es : NEG_SLOPE * es;
    float exs = expf(es);
    float4 hv = H4[gid * 32 + lane];
    float4 acc = make_float4(exs * hv.x, exs * hv.y, exs * hv.z, exs * hv.w);
    float denp = 0.f;

    int begin = g_rowptr[gid];
    int end = g_rowptr[gid + 1];
    for (int base = begin; base < end; base += 32) {
        int j = base + lane;
        int srcj = 0;
        float ex = 0.f;
        if (j < end) {
            srcj = g_esrc[j];
            float e = g_as[srcj] + ad_d;
            e = (e > 0.f) ? e : NEG_SLOPE * e;
            ex = expf(e);
            denp += ex;
        }
        int cnt = end - base; if (cnt > 32) cnt = 32;
        for (int k = 0; k < cnt; k++) {
            int s = __shfl_sync(FULL, srcj, k);
            float exk = __shfl_sync(FULL, ex, k);
            float4 hs = H4[s * 32 + lane];
            acc.x += exk * hs.x;
            acc.y += exk * hs.y;
            acc.z += exk * hs.z;
            acc.w += exk * hs.w;
        }
    }
#pragma unroll
    for (int off = 16; off; off >>= 1)
        denp += __shfl_xor_sync(FULL, denp, off);
    float inv = 1.f / (denp + exs);

    if (layer == 1) {
        const float* b1   = v.p[g_r_b1];
        const float* ln_g = v.p[g_r_lng];
        const float* ln_b = v.p[g_r_lnb];
        float o0 = acc.x * inv + b1[lane * 4 + 0];
        float o1 = acc.y * inv + b1[lane * 4 + 1];
        float o2 = acc.z * inv + b1[lane * 4 + 2];
        float o3 = acc.w * inv + b1[lane * 4 + 3];

        float s = o0 + o1 + o2 + o3;
        float sq = o0 * o0 + o1 * o1 + o2 * o2 + o3 * o3;
#pragma unroll
        for (int off = 16; off; off >>= 1) {
            s  += __shfl_xor_sync(FULL, s, off);
            sq += __shfl_xor_sync(FULL, sq, off);
        }
        float mu = s * (1.f / CC);
        float var = sq * (1.f / CC) - mu * mu;
        float rstd = rsqrtf(var + LN_EPS);

        float y0 = (o0 - mu) * rstd * ln_g[lane * 4 + 0] + ln_b[lane * 4 + 0];
        float y1 = (o1 - mu) * rstd * ln_g[lane * 4 + 1] + ln_b[lane * 4 + 1];
        float y2 = (o2 - mu) * rstd * ln_g[lane * 4 + 2] + ln_b[lane * 4 + 2];
        float y3 = (o3 - mu) * rstd * ln_g[lane * 4 + 3] + ln_b[lane * 4 + 3];
        y0 = (y0 > 0.f) ? y0 : expm1f(y0);
        y1 = (y1 > 0.f) ? y1 : expm1f(y1);
        y2 = (y2 > 0.f) ? y2 : expm1f(y2);
        y3 = (y3 > 0.f) ? y3 : expm1f(y3);

        float* op = outbuf + gid * CC + lane * 4;
        op[0] = y0; op[1] = y1; op[2] = y2; op[3] = y3;
    } else {
        const float* b2 = v.p[g_r_b2];
        float* op = outbuf + gid * CC + lane * 4;
        op[0] = acc.x * inv + b2[lane * 4 + 0];
        op[1] = acc.y * inv + b2[lane * 4 + 1];
        op[2] = acc.z * inv + b2[lane * 4 + 2];
        op[3] = acc.w * inv + b2[lane * 4 + 3];
    }
}

// -----------------------------------------------------------------------------
extern "C" void kernel_launch(void* const* d_in, const int* in_sizes, int n_in,
                              void* d_out, int out_size) {
    // --- input remap by element count (verified: counts, dict order) ---
    int ix = 0, icid = 1, iei = 2, icemb = 3, iW1 = 4, iW2 = 10;
    int vecidx[8];
    int nvec = 0;
    {
        int fx = -1, fcid = -1, fei = -1, fcemb = -1, fW1 = -1, fW2 = -1;
        for (int i = 0; i < n_in; i++) {
            long long s = in_sizes[i];
            if (s == NN * CC) fx = (fx < 0) ? i : fx;
            else if (s == NN || s == 2 * NN) fcid = (fcid < 0) ? i : fcid;
            else if (s == 2LL * EE || s == 4LL * EE) fei = (fei < 0) ? i : fei;
            else if (s == NUM_CELLS * CE) fcemb = (fcemb < 0) ? i : fcemb;
            else if (s == (CC + CE) * CC) fW1 = (fW1 < 0) ? i : fW1;
            else if (s == CC * CC) fW2 = (fW2 < 0) ? i : fW2;
            else if (s == CC && nvec < 8) vecidx[nvec++] = i;
        }
        if (fx >= 0 && fcid >= 0 && fei >= 0 && fcemb >= 0 && fW1 >= 0 &&
            fW2 >= 0 && nvec == 8) {
            ix = fx; icid = fcid; iei = fei; icemb = fcemb; iW1 = fW1; iW2 = fW2;
        } else {
            ix = 0; icid = 1; iei = 2; icemb = 3; iW1 = 4; iW2 = 10;
            vecidx[0] = 5; vecidx[1] = 6; vecidx[2] = 7; vecidx[3] = 8;
            vecidx[4] = 9; vecidx[5] = 11; vecidx[6] = 12; vecidx[7] = 13;
        }
    }

    const float* x_base  = (const float*)d_in[ix];
    const void*  cids    = d_in[icid];
    const void*  ei      = d_in[iei];
    const float* cellemb = (const float*)d_in[icemb];
    const float* W1      = (const float*)d_in[iW1];
    const float* W2      = (const float*)d_in[iW2];
    Vec8 v;
    for (int j = 0; j < 8; j++) v.p[j] = (const float*)d_in[vecidx[j]];
    float* out = (float*)d_out;

    int gemm_blocks = (NN + 63) / 64;
    int node_blocks = (NN * 32 + 255) / 256;
    int nn_blocks   = (NN + 255) / 256;
    int ee_blocks   = (EE + 255) / 256;

    prep_kernel<<<3, 256>>>(ei, cids, v);
    cellw_kernel<<<NUM_CELLS, CC>>>(cellemb, W1);

    // ---- CSR build (once; reused by both layers) ----
    csr_zero_kernel<<<nn_blocks, 256>>>();
    csr_hist_kernel<<<ee_blocks, 256>>>(ei);
    csr_scan1_kernel<<<NCH, 256>>>();
    csr_scan2_kernel<<<1, 32>>>();
    csr_scan3_kernel<<<NCH, 256>>>();
    csr_scatter_kernel<<<ee_blocks, 256>>>(ei);

    // ---- layer 1: gemm(+asad) -> aggregate (x2 into d_out) ----
    gemm_kernel<<<gemm_blocks, 256>>>(x_base, W1, cids, v, 1);
    agg_kernel<<<node_blocks, 256>>>(v, 1, out);

    // ---- layer 2: gemm(+asad) reads x2 from d_out -> aggregate (final) ----
    gemm_kernel<<<gemm_blocks, 256>>>(out, W2, cids, v, 2);
    agg_kernel<<<node_blocks, 256>>>(v, 2, out);
}